// round 16
// baseline (speedup 1.0000x reference)
#include <cuda_runtime.h>
#include <cuda_bf16.h>
#include <cstdint>

#define B_    16
#define N_    1024
#define DIM_  128
#define H_    8
#define DH_   16
#define BH_   (B_*H_)

// ---- scratch (device globals; no allocation) ----
__device__ __align__(16) float g_qf [BH_*N_*DH_];   // Q fp32(tf32, pre-scaled by sc*log2e)
__device__ __align__(16) float g_kf [BH_*N_*DH_];   // K fp32(tf32) [bh][n][d]
__device__ __align__(16) float g_vtf[BH_*DH_*N_];   // V^T fp32(tf32) [bh][d][n]
__device__ __align__(16) float g_sval[B_*N_];       // per-(b,j) validity
__device__ __align__(16) __nv_bfloat16 g_aoh[B_*N_*DIM_];
__device__ __align__(16) __nv_bfloat16 g_aol[B_*N_*DIM_];
__device__ __align__(16) __nv_bfloat16 g_wqt_h[384*128];   // Wqkv^T [n][k]
__device__ __align__(16) __nv_bfloat16 g_wqt_l[384*128];
__device__ __align__(16) __nv_bfloat16 g_wot_h[128*128];   // Wout^T [n][k]
__device__ __align__(16) __nv_bfloat16 g_wot_l[128*128];

// ---- helpers ----
__device__ __forceinline__ void split2(float a, float b, uint32_t& hi, uint32_t& lo) {
    __nv_bfloat162 hp = __floats2bfloat162_rn(a, b);
    hi = *reinterpret_cast<uint32_t*>(&hp);
    __nv_bfloat162 lp = __floats2bfloat162_rn(a - __low2float(hp), b - __high2float(hp));
    lo = *reinterpret_cast<uint32_t*>(&lp);
}
__device__ __forceinline__ float to_tf32(float x) {
    float r; asm("cvt.rna.tf32.f32 %0, %1;" : "=f"(r) : "f"(x)); return r;
}
__device__ __forceinline__ float ex2f(float x) {
    float r; asm("ex2.approx.f32 %0, %1;" : "=f"(r) : "f"(x)); return r;
}
__device__ __forceinline__ void cpa16(void* s, const void* g) {
    uint32_t sa = (uint32_t)__cvta_generic_to_shared(s);
    asm volatile("cp.async.cg.shared.global [%0], [%1], 16;" :: "r"(sa), "l"(g));
}
#define CP_COMMIT() asm volatile("cp.async.commit_group;")
#define CP_WAIT0()  asm volatile("cp.async.wait_group 0;")

__device__ __forceinline__ void mma16816(float* d, const uint32_t* a,
                                         uint32_t b0, uint32_t b1, const float* c)
{
    asm volatile("mma.sync.aligned.m16n8k16.row.col.f32.bf16.bf16.f32 "
        "{%0,%1,%2,%3}, {%4,%5,%6,%7}, {%8,%9}, {%10,%11,%12,%13};"
        : "=f"(d[0]), "=f"(d[1]), "=f"(d[2]), "=f"(d[3])
        : "r"(a[0]), "r"(a[1]), "r"(a[2]), "r"(a[3]), "r"(b0), "r"(b1),
          "f"(c[0]), "f"(c[1]), "f"(c[2]), "f"(c[3]));
}
__device__ __forceinline__ void mma1688t(float* d, const uint32_t* a,
                                         uint32_t b0, uint32_t b1, const float* c)
{
    asm volatile("mma.sync.aligned.m16n8k8.row.col.f32.tf32.tf32.f32 "
        "{%0,%1,%2,%3}, {%4,%5,%6,%7}, {%8,%9}, {%10,%11,%12,%13};"
        : "=f"(d[0]), "=f"(d[1]), "=f"(d[2]), "=f"(d[3])
        : "r"(a[0]), "r"(a[1]), "r"(a[2]), "r"(a[3]), "r"(b0), "r"(b1),
          "f"(c[0]), "f"(c[1]), "f"(c[2]), "f"(c[3]));
}

// ---------------------------------------------------------------------------
// Prep: weights -> bf16 hi/lo [n][k] (blocks 0..511), sval (blocks 512..639).
// Q cols scaled by 128^-0.5 * log2(e).
// ---------------------------------------------------------------------------
__global__ void prep_kernel(const float* __restrict__ Wqkv,
                            const float* __restrict__ Wout,
                            const float* __restrict__ mask,
                            const float* __restrict__ maps)
{
    const float qsc = 0.088388347648318447f * 1.4426950408889634f;
    int blk = blockIdx.x, tid = threadIdx.x;
    if (blk < 384) {
        float w = Wqkv[tid * 384 + blk] * (blk < 128 ? qsc : 1.f);
        __nv_bfloat16 h = __float2bfloat16(w);
        g_wqt_h[blk * 128 + tid] = h;
        g_wqt_l[blk * 128 + tid] = __float2bfloat16(w - __bfloat162float(h));
    } else if (blk < 512) {
        int c2 = blk - 384;
        float w = Wout[tid * 128 + c2];
        __nv_bfloat16 h = __float2bfloat16(w);
        g_wot_h[c2 * 128 + tid] = h;
        g_wot_l[c2 * 128 + tid] = __float2bfloat16(w - __bfloat162float(h));
    } else {
        int r = blk - 512;
        int b = r >> 3;
        int j = (r & 7) * 128 + tid;
        g_sval[b * N_ + j] = (j == 0) ? 1.f : mask[j - 1] * maps[b * (N_ - 1) + j - 1];
    }
}

// ---------------------------------------------------------------------------
// HMMA GEMM (bf16 3-pass), 128x64 tile, 8 warps (each warp = 16 rows).
// B staged once; A register-prefetched one chunk ahead.
// MODE 0: A = x fp32, scatter Q/K tf32 + V^T tf32.  grid (128, 6).
// MODE 1: A = g_aoh/g_aol, out = A@Wout + bias.     grid (128, 2).
// ---------------------------------------------------------------------------
#define KST 24
#define BST 136
template<int MODE>
__global__ __launch_bounds__(256)
void gemm_hmma_kernel(const float* __restrict__ X,
                      const float* __restrict__ bias,
                      float* __restrict__ out)
{
    __shared__ __align__(16) __nv_bfloat16 sAh[128 * KST], sAl[128 * KST];
    __shared__ __align__(16) __nv_bfloat16 sBh[64 * BST],  sBl[64 * BST];

    const int tid = threadIdx.x;
    const int warp = tid >> 5, lane = tid & 31;
    const int g = lane >> 2, t = lane & 3;
    const int row0 = blockIdx.x * 128;
    const int col0 = blockIdx.y * 64;

    const __nv_bfloat16* Bth = (MODE == 0) ? g_wqt_h : g_wot_h;
    const __nv_bfloat16* Btl = (MODE == 0) ? g_wqt_l : g_wot_l;

    // ---- stage entire B tile (64 cols x 128 k, hi+lo) once ----
    #pragma unroll
    for (int i = tid; i < 1024; i += 256) {
        int c = i >> 4, ch = i & 15;
        *(uint4*)&sBh[c * BST + ch * 8] = *(const uint4*)(Bth + (col0 + c) * 128 + ch * 8);
        *(uint4*)&sBl[c * BST + ch * 8] = *(const uint4*)(Btl + (col0 + c) * 128 + ch * 8);
    }

    float C[8][4];
    #pragma unroll
    for (int nb = 0; nb < 8; nb++)
        #pragma unroll
        for (int i = 0; i < 4; i++) C[nb][i] = 0.f;

    // ---- A prefetch: each thread stages one 8-element half-row ----
    const int ar = tid >> 1, ah2 = (tid & 1) * 8;
    float4 va[2];      // MODE 0
    uint4 vah, val;    // MODE 1
    if (MODE == 0) {
        const float* src = X + (row0 + ar) * DIM_ + ah2;
        va[0] = *reinterpret_cast<const float4*>(src);
        va[1] = *reinterpret_cast<const float4*>(src + 4);
    } else {
        vah = *(const uint4*)(g_aoh + (row0 + ar) * DIM_ + ah2);
        val = *(const uint4*)(g_aol + (row0 + ar) * DIM_ + ah2);
    }

    #pragma unroll
    for (int kc = 0; kc < 8; kc++) {
        // ---- store prefetched A chunk ----
        if (MODE == 0) {
            uint32_t h[4], l[4];
            split2(va[0].x, va[0].y, h[0], l[0]);
            split2(va[0].z, va[0].w, h[1], l[1]);
            split2(va[1].x, va[1].y, h[2], l[2]);
            split2(va[1].z, va[1].w, h[3], l[3]);
            *(uint4*)&sAh[ar * KST + ah2] = make_uint4(h[0], h[1], h[2], h[3]);
            *(uint4*)&sAl[ar * KST + ah2] = make_uint4(l[0], l[1], l[2], l[3]);
        } else {
            *(uint4*)&sAh[ar * KST + ah2] = vah;
            *(uint4*)&sAl[ar * KST + ah2] = val;
        }
        __syncthreads();

        // ---- prefetch next chunk (overlaps mma section) ----
        if (kc < 7) {
            if (MODE == 0) {
                const float* src = X + (row0 + ar) * DIM_ + (kc + 1) * 16 + ah2;
                va[0] = *reinterpret_cast<const float4*>(src);
                va[1] = *reinterpret_cast<const float4*>(src + 4);
            } else {
                vah = *(const uint4*)(g_aoh + (row0 + ar) * DIM_ + (kc + 1) * 16 + ah2);
                val = *(const uint4*)(g_aol + (row0 + ar) * DIM_ + (kc + 1) * 16 + ah2);
            }
        }

        uint32_t aH[4], aL[4];
        {
            int r = warp * 16 + g;
            aH[0] = *(const uint32_t*)&sAh[r * KST + 2 * t];
            aH[1] = *(const uint32_t*)&sAh[(r + 8) * KST + 2 * t];
            aH[2] = *(const uint32_t*)&sAh[r * KST + 8 + 2 * t];
            aH[3] = *(const uint32_t*)&sAh[(r + 8) * KST + 8 + 2 * t];
            aL[0] = *(const uint32_t*)&sAl[r * KST + 2 * t];
            aL[1] = *(const uint32_t*)&sAl[(r + 8) * KST + 2 * t];
            aL[2] = *(const uint32_t*)&sAl[r * KST + 8 + 2 * t];
            aL[3] = *(const uint32_t*)&sAl[(r + 8) * KST + 8 + 2 * t];
        }
        #pragma unroll
        for (int nb = 0; nb < 8; nb++) {
            const __nv_bfloat16* br = &sBh[(nb * 8 + g) * BST + kc * 16 + 2 * t];
            uint32_t bh0 = *(const uint32_t*)br;
            uint32_t bh1 = *(const uint32_t*)(br + 8);
            const __nv_bfloat16* brl = &sBl[(nb * 8 + g) * BST + kc * 16 + 2 * t];
            uint32_t bl0 = *(const uint32_t*)brl;
            uint32_t bl1 = *(const uint32_t*)(brl + 8);
            mma16816(C[nb], aH, bh0, bh1, C[nb]);
            mma16816(C[nb], aH, bl0, bl1, C[nb]);
            mma16816(C[nb], aL, bh0, bh1, C[nb]);
        }
        if (kc < 7) __syncthreads();
    }

    if (MODE == 0) {
        const int part = col0 >> 7;   // 0=Q, 1=K, 2=V
        int grow = row0 + warp * 16 + g;
        int bq = grow >> 10, n = grow & (N_ - 1);
        #pragma unroll
        for (int nb = 0; nb < 8; nb++) {
            int cc = (col0 + nb * 8 + 2 * t) & 127;
            int hh = cc >> 4, dd = cc & 15;
            if (part == 0) {
                int idx0 = ((bq * H_ + hh) * N_ + n) * DH_ + dd;
                *(float2*)&g_qf[idx0] = make_float2(to_tf32(C[nb][0]), to_tf32(C[nb][1]));
                *(float2*)&g_qf[idx0 + 8 * DH_] = make_float2(to_tf32(C[nb][2]), to_tf32(C[nb][3]));
            } else if (part == 1) {
                int idx0 = ((bq * H_ + hh) * N_ + n) * DH_ + dd;
                *(float2*)&g_kf[idx0] = make_float2(to_tf32(C[nb][0]), to_tf32(C[nb][1]));
                *(float2*)&g_kf[idx0 + 8 * DH_] = make_float2(to_tf32(C[nb][2]), to_tf32(C[nb][3]));
            } else {
                float* v0 = g_vtf + ((bq * H_ + hh) * DH_ + dd) * N_ + n;
                float* v1 = v0 + N_;
                v0[0] = to_tf32(C[nb][0]);
                v1[0] = to_tf32(C[nb][1]);
                v0[8] = to_tf32(C[nb][2]);
                v1[8] = to_tf32(C[nb][3]);
            }
        }
    } else {
        int grow = row0 + warp * 16 + g;
        #pragma unroll
        for (int nb = 0; nb < 8; nb++) {
            int col = col0 + nb * 8 + 2 * t;
            float b0 = bias[col], b1 = bias[col + 1];
            *(float2*)&out[grow * DIM_ + col] =
                make_float2(C[nb][0] + b0, C[nb][1] + b1);
            *(float2*)&out[(grow + 8) * DIM_ + col] =
                make_float2(C[nb][2] + b0, C[nb][3] + b1);
        }
    }
}

// ---------------------------------------------------------------------------
// TF32 flash attention: cp.async double-buffered staging, exp2 path,
// implicit-truncation PV (truncation scale cancels in p/l). UNCHANGED.
// ---------------------------------------------------------------------------
#define QSTF 20
#define KSTF 40
#define VSTF 72
__global__ __launch_bounds__(128, 5)
void attn_tf32_kernel()
{
    __shared__ float sQ[128 * QSTF];
    __shared__ float sK[2][64 * KSTF];
    __shared__ float sVt[2][16 * VSTF];
    __shared__ float sval[2][64];

    const int tid  = threadIdx.x;
    const int warp = tid >> 5;
    const int lane = tid & 31;
    const int g = lane >> 2;
    const int t = lane & 3;
    const int qt = blockIdx.x, h = blockIdx.y, b = blockIdx.z;
    const int bh = b * H_ + h;
    const int n0 = qt * 128;

    const int kr  = tid >> 1, khf = (tid & 1) * 8;
    const int vd  = tid >> 3, vc0 = (tid & 7) * 4;
    auto stage = [&](int buf, int k0) {
        cpa16(&sK[buf][kr * KSTF + khf],     &g_kf[(bh * N_ + k0 + kr) * DH_ + khf]);
        cpa16(&sK[buf][kr * KSTF + khf + 4], &g_kf[(bh * N_ + k0 + kr) * DH_ + khf + 4]);
        cpa16(&sVt[buf][vd * VSTF + vc0],      &g_vtf[(bh * DH_ + vd) * N_ + k0 + vc0]);
        cpa16(&sVt[buf][vd * VSTF + vc0 + 32], &g_vtf[(bh * DH_ + vd) * N_ + k0 + vc0 + 32]);
        if (tid < 16) cpa16(&sval[buf][tid * 4], &g_sval[b * N_ + k0 + tid * 4]);
    };

    {
        const float* src = g_qf + (bh * N_ + n0 + tid) * DH_;
        #pragma unroll
        for (int q = 0; q < 4; q++)
            *(float4*)&sQ[tid * QSTF + q * 4] = *(const float4*)(src + q * 4);
    }
    stage(0, 0);
    CP_COMMIT();
    __syncthreads();

    uint32_t aQ[2][2][4];
    #pragma unroll
    for (int rb = 0; rb < 2; rb++) {
        int r = warp * 32 + rb * 16 + g;
        #pragma unroll
        for (int dk = 0; dk < 2; dk++) {
            float2 f0 = *(const float2*)&sQ[r * QSTF + dk * 8 + 2 * t];
            float2 f1 = *(const float2*)&sQ[(r + 8) * QSTF + dk * 8 + 2 * t];
            aQ[rb][dk][0] = __float_as_uint(f0.x);
            aQ[rb][dk][1] = __float_as_uint(f1.x);
            aQ[rb][dk][2] = __float_as_uint(f0.y);
            aQ[rb][dk][3] = __float_as_uint(f1.y);
        }
    }

    float O[2][2][4];
    #pragma unroll
    for (int rb = 0; rb < 2; rb++)
        #pragma unroll
        for (int db = 0; db < 2; db++)
            #pragma unroll
            for (int i = 0; i < 4; i++) O[rb][db][i] = 0.f;
    float lac[2][2] = {{0.f, 0.f}, {0.f, 0.f}};

    for (int kt = 0; kt < 16; kt++) {
        const int cb = kt & 1;
        CP_WAIT0();
        __syncthreads();
        if (kt < 15) { stage(cb ^ 1, (kt + 1) * 64); CP_COMMIT(); }

        const float* sKc = sK[cb];
        const float* sVc = sVt[cb];
        const float* svc = sval[cb];

        #pragma unroll
        for (int half = 0; half < 2; half++) {
            float S[2][4][4];
            #pragma unroll
            for (int kb4 = 0; kb4 < 4; kb4++) {
                int kb = half * 4 + kb4;
                const float* krp = &sKc[(kb * 8 + g) * KSTF + 2 * t];
                float2 bk0 = *(const float2*)krp;
                float2 bk1 = *(const float2*)(krp + 8);
                uint32_t b00 = __float_as_uint(bk0.x), b01 = __float_as_uint(bk0.y);
                uint32_t b10 = __float_as_uint(bk1.x), b11 = __float_as_uint(bk1.y);
                #pragma unroll
                for (int rb = 0; rb < 2; rb++) {
                    float z[4] = {0.f, 0.f, 0.f, 0.f};
                    mma1688t(S[rb][kb4], aQ[rb][0], b00, b01, z);
                    mma1688t(S[rb][kb4], aQ[rb][1], b10, b11, S[rb][kb4]);
                }
            }

            #pragma unroll
            for (int kb4 = 0; kb4 < 4; kb4++) {
                int kb = half * 4 + kb4;
                float v0 = svc[kb * 8 + 2 * t];
                float v1 = svc[kb * 8 + 2 * t + 1];
                #pragma unroll
                for (int rb = 0; rb < 2; rb++) {
                    float p0 = __uint_as_float(__float_as_uint(ex2f(S[rb][kb4][0]) * v0) & 0xFFFFE000u);
                    float p1 = __uint_as_float(__float_as_uint(ex2f(S[rb][kb4][1]) * v1) & 0xFFFFE000u);
                    float p2 = __uint_as_float(__float_as_uint(ex2f(S[rb][kb4][2]) * v0) & 0xFFFFE000u);
                    float p3 = __uint_as_float(__float_as_uint(ex2f(S[rb][kb4][3]) * v1) & 0xFFFFE000u);
                    S[rb][kb4][0] = p0; S[rb][kb4][1] = p1;
                    S[rb][kb4][2] = p2; S[rb][kb4][3] = p3;
                    lac[rb][0] += p0 + p1;
                    lac[rb][1] += p2 + p3;
                }
            }

            #pragma unroll
            for (int kb4 = 0; kb4 < 4; kb4++) {
                int keyb = half * 32 + kb4 * 8;
                uint32_t aP[2][4];
                #pragma unroll
                for (int rb = 0; rb < 2; rb++) {
                    aP[rb][0] = __float_as_uint(S[rb][kb4][0]);
                    aP[rb][1] = __float_as_uint(S[rb][kb4][2]);
                    aP[rb][2] = __float_as_uint(S[rb][kb4][1]);
                    aP[rb][3] = __float_as_uint(S[rb][kb4][3]);
                }
                #pragma unroll
                for (int db = 0; db < 2; db++) {
                    float2 bv = *(const float2*)&sVc[(db * 8 + g) * VSTF + keyb + 2 * t];
                    uint32_t b0 = __float_as_uint(bv.x), b1 = __float_as_uint(bv.y);
                    #pragma unroll
                    for (int rb = 0; rb < 2; rb++)
                        mma1688t(O[rb][db], aP[rb], b0, b1, O[rb][db]);
                }
            }
        }
    }

    #pragma unroll
    for (int rb = 0; rb < 2; rb++)
        #pragma unroll
        for (int hh = 0; hh < 2; hh++) {
            lac[rb][hh] += __shfl_xor_sync(0xffffffffu, lac[rb][hh], 1);
            lac[rb][hh] += __shfl_xor_sync(0xffffffffu, lac[rb][hh], 2);
        }

    #pragma unroll
    for (int rb = 0; rb < 2; rb++) {
        int r = n0 + warp * 32 + rb * 16 + g;
        float inv0 = 1.f / lac[rb][0];
        float inv1 = 1.f / lac[rb][1];
        #pragma unroll
        for (int db = 0; db < 2; db++) {
            int cbn = h * DH_ + db * 8 + 2 * t;
            int idx0 = (b * N_ + r) * DIM_ + cbn;
            int idx1 = (b * N_ + r + 8) * DIM_ + cbn;
            uint32_t hi, lo;
            split2(O[rb][db][0] * inv0, O[rb][db][1] * inv0, hi, lo);
            *(uint32_t*)&g_aoh[idx0] = hi; *(uint32_t*)&g_aol[idx0] = lo;
            split2(O[rb][db][2] * inv1, O[rb][db][3] * inv1, hi, lo);
            *(uint32_t*)&g_aoh[idx1] = hi; *(uint32_t*)&g_aol[idx1] = lo;
        }
    }
}

// ---------------------------------------------------------------------------
extern "C" void kernel_launch(void* const* d_in, const int* in_sizes, int n_in,
                              void* d_out, int out_size)
{
    const float* x    = (const float*)d_in[0];
    const float* mask = (const float*)d_in[1];
    const float* maps = (const float*)d_in[2];
    const float* Wqkv = (const float*)d_in[3];
    const float* Wout = (const float*)d_in[4];
    const float* bout = (const float*)d_in[5];
    float* out = (float*)d_out;

    prep_kernel<<<640, 128>>>(Wqkv, Wout, mask, maps);
    gemm_hmma_kernel<0><<<dim3(128, 6), 256>>>(x, nullptr, nullptr);
    attn_tf32_kernel<<<dim3(8, H_, B_), 128>>>();
    gemm_hmma_kernel<1><<<dim3(128, 2), 256>>>(nullptr, bout, out);
}

// round 17
// speedup vs baseline: 1.4804x; 1.4804x over previous
#include <cuda_runtime.h>
#include <cuda_bf16.h>
#include <cstdint>

#define B_    16
#define N_    1024
#define DIM_  128
#define H_    8
#define DH_   16
#define BH_   (B_*H_)

// ---- scratch (device globals; no allocation) ----
__device__ __align__(16) float g_qf [BH_*N_*DH_];   // Q fp32(tf32, pre-scaled by sc*log2e)
__device__ __align__(16) float g_kf [BH_*N_*DH_];   // K fp32(tf32) [bh][n][d]
__device__ __align__(16) float g_vtf[BH_*DH_*N_];   // V^T fp32(tf32) [bh][d][n]
__device__ __align__(16) float g_sval[B_*N_];       // per-(b,j) validity
__device__ __align__(16) float g_aof[B_*N_*DIM_];   // attn out, fp32 tf32-rounded
__device__ __align__(16) float g_wqt[384*128];      // Wqkv^T [n][k] fp32 tf32 (Q cols pre-scaled)
__device__ __align__(16) float g_wot[128*128];      // Wout^T [n][k] fp32 tf32

// ---- helpers ----
__device__ __forceinline__ float to_tf32(float x) {
    float r; asm("cvt.rna.tf32.f32 %0, %1;" : "=f"(r) : "f"(x)); return r;
}
__device__ __forceinline__ float ex2f(float x) {
    float r; asm("ex2.approx.f32 %0, %1;" : "=f"(r) : "f"(x)); return r;
}
__device__ __forceinline__ void cpa16(void* s, const void* g) {
    uint32_t sa = (uint32_t)__cvta_generic_to_shared(s);
    asm volatile("cp.async.cg.shared.global [%0], [%1], 16;" :: "r"(sa), "l"(g));
}
#define CP_COMMIT() asm volatile("cp.async.commit_group;")
#define CP_WAIT0()  asm volatile("cp.async.wait_group 0;")

__device__ __forceinline__ void mma1688t(float* d, const uint32_t* a,
                                         uint32_t b0, uint32_t b1, const float* c)
{
    asm volatile("mma.sync.aligned.m16n8k8.row.col.f32.tf32.tf32.f32 "
        "{%0,%1,%2,%3}, {%4,%5,%6,%7}, {%8,%9}, {%10,%11,%12,%13};"
        : "=f"(d[0]), "=f"(d[1]), "=f"(d[2]), "=f"(d[3])
        : "r"(a[0]), "r"(a[1]), "r"(a[2]), "r"(a[3]), "r"(b0), "r"(b1),
          "f"(c[0]), "f"(c[1]), "f"(c[2]), "f"(c[3]));
}

// ---------------------------------------------------------------------------
// Prep: weights -> fp32 tf32-rounded [n][k] (blocks 0..511), sval (512..639).
// Q cols scaled by 128^-0.5 * log2(e).
// ---------------------------------------------------------------------------
__global__ void prep_kernel(const float* __restrict__ Wqkv,
                            const float* __restrict__ Wout,
                            const float* __restrict__ mask,
                            const float* __restrict__ maps)
{
    const float qsc = 0.088388347648318447f * 1.4426950408889634f;
    int blk = blockIdx.x, tid = threadIdx.x;
    if (blk < 384) {
        float w = Wqkv[tid * 384 + blk] * (blk < 128 ? qsc : 1.f);
        g_wqt[blk * 128 + tid] = to_tf32(w);
    } else if (blk < 512) {
        int c2 = blk - 384;
        g_wot[c2 * 128 + tid] = to_tf32(Wout[tid * 128 + c2]);
    } else {
        int r = blk - 512;
        int b = r >> 3;
        int j = (r & 7) * 128 + tid;
        g_sval[b * N_ + j] = (j == 0) ? 1.f : mask[j - 1] * maps[b * (N_ - 1) + j - 1];
    }
}

// ---------------------------------------------------------------------------
// TF32 single-pass GEMM, 128x64 tile, 4 warps (R15 shape).
// B staged once (fp32 tf32, stride 136 conflict-free); A register-prefetched.
// MODE 0: A = x fp32 (cvt.rna on staging), scatter Q/K tf32 + V^T tf32.  grid (128, 6).
// MODE 1: A = g_aof (already tf32-rounded), out = A@Wout + bias.         grid (128, 2).
// ---------------------------------------------------------------------------
#define AST 24
#define BSTF 136
template<int MODE>
__global__ __launch_bounds__(128)
void gemm_tf32_kernel(const float* __restrict__ X,
                      const float* __restrict__ bias,
                      float* __restrict__ out)
{
    __shared__ float sA[128 * AST];     // 12 KB
    __shared__ float sB[64 * BSTF];     // 34.8 KB  (total 46.8 KB < 48)

    const int tid = threadIdx.x;
    const int warp = tid >> 5, lane = tid & 31;
    const int g = lane >> 2, t = lane & 3;
    const int row0 = blockIdx.x * 128;
    const int col0 = blockIdx.y * 64;

    const float* Bt = (MODE == 0) ? g_wqt : g_wot;
    const float* Ain = (MODE == 0) ? X : g_aof;

    // ---- stage entire B tile (64 cols x 128 k) once ----
    #pragma unroll
    for (int i = tid; i < 2048; i += 128) {
        int c = i >> 5, ch = i & 31;
        *(float4*)&sB[c * BSTF + ch * 4] = *(const float4*)(Bt + (col0 + c) * 128 + ch * 4);
    }

    float C[2][8][4];
    #pragma unroll
    for (int rb = 0; rb < 2; rb++)
        #pragma unroll
        for (int nb = 0; nb < 8; nb++)
            #pragma unroll
            for (int i = 0; i < 4; i++) C[rb][nb][i] = 0.f;

    // ---- A prefetch (row = tid, 16 floats per chunk) ----
    float4 va[4];
    {
        const float* src = Ain + (row0 + tid) * DIM_;
        #pragma unroll
        for (int q = 0; q < 4; q++) va[q] = *reinterpret_cast<const float4*>(src + q * 4);
    }

    #pragma unroll
    for (int kc = 0; kc < 8; kc++) {
        // ---- store prefetched A chunk (MODE 0: round to tf32) ----
        #pragma unroll
        for (int q = 0; q < 4; q++) {
            float4 v = va[q];
            if (MODE == 0) {
                v.x = to_tf32(v.x); v.y = to_tf32(v.y);
                v.z = to_tf32(v.z); v.w = to_tf32(v.w);
            }
            *(float4*)&sA[tid * AST + q * 4] = v;
        }
        __syncthreads();

        // ---- prefetch next chunk (overlaps mma section) ----
        if (kc < 7) {
            const float* src = Ain + (row0 + tid) * DIM_ + (kc + 1) * 16;
            #pragma unroll
            for (int q = 0; q < 4; q++) va[q] = *reinterpret_cast<const float4*>(src + q * 4);
        }

        // ---- A fragments (even/odd k-permutation, same as attn) ----
        uint32_t aF[2][2][4];
        #pragma unroll
        for (int rb = 0; rb < 2; rb++) {
            int r = warp * 32 + rb * 16 + g;
            #pragma unroll
            for (int dk = 0; dk < 2; dk++) {
                float2 f0 = *(const float2*)&sA[r * AST + dk * 8 + 2 * t];
                float2 f1 = *(const float2*)&sA[(r + 8) * AST + dk * 8 + 2 * t];
                aF[rb][dk][0] = __float_as_uint(f0.x);
                aF[rb][dk][1] = __float_as_uint(f1.x);
                aF[rb][dk][2] = __float_as_uint(f0.y);
                aF[rb][dk][3] = __float_as_uint(f1.y);
            }
        }
        #pragma unroll
        for (int nb = 0; nb < 8; nb++) {
            #pragma unroll
            for (int dk = 0; dk < 2; dk++) {
                float2 bv = *(const float2*)&sB[(nb * 8 + g) * BSTF + kc * 16 + dk * 8 + 2 * t];
                uint32_t b0 = __float_as_uint(bv.x), b1 = __float_as_uint(bv.y);
                #pragma unroll
                for (int rb = 0; rb < 2; rb++)
                    mma1688t(C[rb][nb], aF[rb][dk], b0, b1, C[rb][nb]);
            }
        }
        if (kc < 7) __syncthreads();
    }

    if (MODE == 0) {
        const int part = col0 >> 7;   // 0=Q, 1=K, 2=V
        #pragma unroll
        for (int rb = 0; rb < 2; rb++) {
            int grow = row0 + warp * 32 + rb * 16 + g;
            int bq = grow >> 10, n = grow & (N_ - 1);
            #pragma unroll
            for (int nb = 0; nb < 8; nb++) {
                int cc = (col0 + nb * 8 + 2 * t) & 127;
                int hh = cc >> 4, dd = cc & 15;
                if (part == 0) {
                    int idx0 = ((bq * H_ + hh) * N_ + n) * DH_ + dd;
                    *(float2*)&g_qf[idx0] = make_float2(to_tf32(C[rb][nb][0]), to_tf32(C[rb][nb][1]));
                    *(float2*)&g_qf[idx0 + 8 * DH_] = make_float2(to_tf32(C[rb][nb][2]), to_tf32(C[rb][nb][3]));
                } else if (part == 1) {
                    int idx0 = ((bq * H_ + hh) * N_ + n) * DH_ + dd;
                    *(float2*)&g_kf[idx0] = make_float2(to_tf32(C[rb][nb][0]), to_tf32(C[rb][nb][1]));
                    *(float2*)&g_kf[idx0 + 8 * DH_] = make_float2(to_tf32(C[rb][nb][2]), to_tf32(C[rb][nb][3]));
                } else {
                    float* v0 = g_vtf + ((bq * H_ + hh) * DH_ + dd) * N_ + n;
                    float* v1 = v0 + N_;
                    v0[0] = to_tf32(C[rb][nb][0]);
                    v1[0] = to_tf32(C[rb][nb][1]);
                    v0[8] = to_tf32(C[rb][nb][2]);
                    v1[8] = to_tf32(C[rb][nb][3]);
                }
            }
        }
    } else {
        #pragma unroll
        for (int rb = 0; rb < 2; rb++) {
            int grow = row0 + warp * 32 + rb * 16 + g;
            #pragma unroll
            for (int nb = 0; nb < 8; nb++) {
                int col = col0 + nb * 8 + 2 * t;
                float b0 = bias[col], b1 = bias[col + 1];
                *(float2*)&out[grow * DIM_ + col] =
                    make_float2(C[rb][nb][0] + b0, C[rb][nb][1] + b1);
                *(float2*)&out[(grow + 8) * DIM_ + col] =
                    make_float2(C[rb][nb][2] + b0, C[rb][nb][3] + b1);
            }
        }
    }
}

// ---------------------------------------------------------------------------
// TF32 flash attention: cp.async double-buffered staging, exp2 path,
// implicit-truncation PV. Epilogue now writes fp32 tf32-rounded g_aof.
// ---------------------------------------------------------------------------
#define QSTF 20
#define KSTF 40
#define VSTF 72
__global__ __launch_bounds__(128, 5)
void attn_tf32_kernel()
{
    __shared__ float sQ[128 * QSTF];
    __shared__ float sK[2][64 * KSTF];
    __shared__ float sVt[2][16 * VSTF];
    __shared__ float sval[2][64];

    const int tid  = threadIdx.x;
    const int warp = tid >> 5;
    const int lane = tid & 31;
    const int g = lane >> 2;
    const int t = lane & 3;
    const int qt = blockIdx.x, h = blockIdx.y, b = blockIdx.z;
    const int bh = b * H_ + h;
    const int n0 = qt * 128;

    const int kr  = tid >> 1, khf = (tid & 1) * 8;
    const int vd  = tid >> 3, vc0 = (tid & 7) * 4;
    auto stage = [&](int buf, int k0) {
        cpa16(&sK[buf][kr * KSTF + khf],     &g_kf[(bh * N_ + k0 + kr) * DH_ + khf]);
        cpa16(&sK[buf][kr * KSTF + khf + 4], &g_kf[(bh * N_ + k0 + kr) * DH_ + khf + 4]);
        cpa16(&sVt[buf][vd * VSTF + vc0],      &g_vtf[(bh * DH_ + vd) * N_ + k0 + vc0]);
        cpa16(&sVt[buf][vd * VSTF + vc0 + 32], &g_vtf[(bh * DH_ + vd) * N_ + k0 + vc0 + 32]);
        if (tid < 16) cpa16(&sval[buf][tid * 4], &g_sval[b * N_ + k0 + tid * 4]);
    };

    {
        const float* src = g_qf + (bh * N_ + n0 + tid) * DH_;
        #pragma unroll
        for (int q = 0; q < 4; q++)
            *(float4*)&sQ[tid * QSTF + q * 4] = *(const float4*)(src + q * 4);
    }
    stage(0, 0);
    CP_COMMIT();
    __syncthreads();

    uint32_t aQ[2][2][4];
    #pragma unroll
    for (int rb = 0; rb < 2; rb++) {
        int r = warp * 32 + rb * 16 + g;
        #pragma unroll
        for (int dk = 0; dk < 2; dk++) {
            float2 f0 = *(const float2*)&sQ[r * QSTF + dk * 8 + 2 * t];
            float2 f1 = *(const float2*)&sQ[(r + 8) * QSTF + dk * 8 + 2 * t];
            aQ[rb][dk][0] = __float_as_uint(f0.x);
            aQ[rb][dk][1] = __float_as_uint(f1.x);
            aQ[rb][dk][2] = __float_as_uint(f0.y);
            aQ[rb][dk][3] = __float_as_uint(f1.y);
        }
    }

    float O[2][2][4];
    #pragma unroll
    for (int rb = 0; rb < 2; rb++)
        #pragma unroll
        for (int db = 0; db < 2; db++)
            #pragma unroll
            for (int i = 0; i < 4; i++) O[rb][db][i] = 0.f;
    float lac[2][2] = {{0.f, 0.f}, {0.f, 0.f}};

    for (int kt = 0; kt < 16; kt++) {
        const int cb = kt & 1;
        CP_WAIT0();
        __syncthreads();
        if (kt < 15) { stage(cb ^ 1, (kt + 1) * 64); CP_COMMIT(); }

        const float* sKc = sK[cb];
        const float* sVc = sVt[cb];
        const float* svc = sval[cb];

        #pragma unroll
        for (int half = 0; half < 2; half++) {
            float S[2][4][4];
            #pragma unroll
            for (int kb4 = 0; kb4 < 4; kb4++) {
                int kb = half * 4 + kb4;
                const float* krp = &sKc[(kb * 8 + g) * KSTF + 2 * t];
                float2 bk0 = *(const float2*)krp;
                float2 bk1 = *(const float2*)(krp + 8);
                uint32_t b00 = __float_as_uint(bk0.x), b01 = __float_as_uint(bk0.y);
                uint32_t b10 = __float_as_uint(bk1.x), b11 = __float_as_uint(bk1.y);
                #pragma unroll
                for (int rb = 0; rb < 2; rb++) {
                    float z[4] = {0.f, 0.f, 0.f, 0.f};
                    mma1688t(S[rb][kb4], aQ[rb][0], b00, b01, z);
                    mma1688t(S[rb][kb4], aQ[rb][1], b10, b11, S[rb][kb4]);
                }
            }

            #pragma unroll
            for (int kb4 = 0; kb4 < 4; kb4++) {
                int kb = half * 4 + kb4;
                float v0 = svc[kb * 8 + 2 * t];
                float v1 = svc[kb * 8 + 2 * t + 1];
                #pragma unroll
                for (int rb = 0; rb < 2; rb++) {
                    float p0 = __uint_as_float(__float_as_uint(ex2f(S[rb][kb4][0]) * v0) & 0xFFFFE000u);
                    float p1 = __uint_as_float(__float_as_uint(ex2f(S[rb][kb4][1]) * v1) & 0xFFFFE000u);
                    float p2 = __uint_as_float(__float_as_uint(ex2f(S[rb][kb4][2]) * v0) & 0xFFFFE000u);
                    float p3 = __uint_as_float(__float_as_uint(ex2f(S[rb][kb4][3]) * v1) & 0xFFFFE000u);
                    S[rb][kb4][0] = p0; S[rb][kb4][1] = p1;
                    S[rb][kb4][2] = p2; S[rb][kb4][3] = p3;
                    lac[rb][0] += p0 + p1;
                    lac[rb][1] += p2 + p3;
                }
            }

            #pragma unroll
            for (int kb4 = 0; kb4 < 4; kb4++) {
                int keyb = half * 32 + kb4 * 8;
                uint32_t aP[2][4];
                #pragma unroll
                for (int rb = 0; rb < 2; rb++) {
                    aP[rb][0] = __float_as_uint(S[rb][kb4][0]);
                    aP[rb][1] = __float_as_uint(S[rb][kb4][2]);
                    aP[rb][2] = __float_as_uint(S[rb][kb4][1]);
                    aP[rb][3] = __float_as_uint(S[rb][kb4][3]);
                }
                #pragma unroll
                for (int db = 0; db < 2; db++) {
                    float2 bv = *(const float2*)&sVc[(db * 8 + g) * VSTF + keyb + 2 * t];
                    uint32_t b0 = __float_as_uint(bv.x), b1 = __float_as_uint(bv.y);
                    #pragma unroll
                    for (int rb = 0; rb < 2; rb++)
                        mma1688t(O[rb][db], aP[rb], b0, b1, O[rb][db]);
                }
            }
        }
    }

    #pragma unroll
    for (int rb = 0; rb < 2; rb++)
        #pragma unroll
        for (int hh = 0; hh < 2; hh++) {
            lac[rb][hh] += __shfl_xor_sync(0xffffffffu, lac[rb][hh], 1);
            lac[rb][hh] += __shfl_xor_sync(0xffffffffu, lac[rb][hh], 2);
        }

    #pragma unroll
    for (int rb = 0; rb < 2; rb++) {
        int r = n0 + warp * 32 + rb * 16 + g;
        float inv0 = 1.f / lac[rb][0];
        float inv1 = 1.f / lac[rb][1];
        #pragma unroll
        for (int db = 0; db < 2; db++) {
            int cbn = h * DH_ + db * 8 + 2 * t;
            int idx0 = (b * N_ + r) * DIM_ + cbn;
            int idx1 = (b * N_ + r + 8) * DIM_ + cbn;
            *(float2*)&g_aof[idx0] =
                make_float2(to_tf32(O[rb][db][0] * inv0), to_tf32(O[rb][db][1] * inv0));
            *(float2*)&g_aof[idx1] =
                make_float2(to_tf32(O[rb][db][2] * inv1), to_tf32(O[rb][db][3] * inv1));
        }
    }
}

// ---------------------------------------------------------------------------
extern "C" void kernel_launch(void* const* d_in, const int* in_sizes, int n_in,
                              void* d_out, int out_size)
{
    const float* x    = (const float*)d_in[0];
    const float* mask = (const float*)d_in[1];
    const float* maps = (const float*)d_in[2];
    const float* Wqkv = (const float*)d_in[3];
    const float* Wout = (const float*)d_in[4];
    const float* bout = (const float*)d_in[5];
    float* out = (float*)d_out;

    prep_kernel<<<640, 128>>>(Wqkv, Wout, mask, maps);
    gemm_tf32_kernel<0><<<dim3(128, 6), 128>>>(x, nullptr, nullptr);
    attn_tf32_kernel<<<dim3(8, H_, B_), 128>>>();
    gemm_tf32_kernel<1><<<dim3(128, 2), 128>>>(nullptr, bout, out);
}